// round 11
// baseline (speedup 1.0000x reference)
#include <cuda_runtime.h>
#include <cuda_fp16.h>
#include <math_constants.h>
#include <cstdint>

// Problem constants
#define MAXN 100000
#define MAXE 1600000
#define D 128
#define DOUT 47
#define BN_EPS 1e-5f

// Scratch (device globals; allocation-free per harness rules)
__device__ __half g_A[(size_t)MAXN * D];   // GEMM output (unscaled), fp16
__device__ __half g_Ch[(size_t)MAXN * D];  // h1 (post BN+ReLU), fp16
__device__ float  g_dinv[MAXN];            // 1/sqrt(deg)
__device__ float  g_bn_s[D];               // fused BN scale
__device__ float  g_bn_t[D];               // fused BN bias
__device__ int    g_cnt[MAXN];             // dst histogram (edges only)
__device__ int    g_off[MAXN];             // exclusive prefix of g_cnt
__device__ int    g_cursor[MAXN];          // scatter cursors
__device__ int    g_es[MAXE];              // src ids, sorted by dst
__device__ int    g_bsum[64];              // scan block sums
__device__ int    g_is64;                  // edge_index dtype flag

// ---------------------------------------------------------------------------
// cnt_zero + edge-index dtype detection fused.
// ---------------------------------------------------------------------------
__global__ void cnt_zero_detect(const unsigned int* __restrict__ ei32, int e, int n) {
    int i = blockIdx.x * blockDim.x + threadIdx.x;
    if (i < n) g_cnt[i] = 0;
    if (blockIdx.x == 0 && threadIdx.x == 0) {
        int is64 = 1;
        int lim = (e < 64) ? e : 64;
        for (int k = 0; k < lim; k++) {
            if (ei32[2 * k + 1] != 0u) { is64 = 0; break; }
        }
        g_is64 = is64;
    }
}

__device__ __forceinline__ int load_idx(const void* __restrict__ ei, int e,
                                        int which, int i) {
    if (g_is64) {
        const long long* p = (const long long*)ei;
        return (int)p[(size_t)which * e + i];
    } else {
        const int* p = (const int*)ei;
        return p[(size_t)which * e + i];
    }
}

// ---------------------------------------------------------------------------
// Counting sort by dst: histogram -> scan -> scatter ; degrees ; BN prep
// ---------------------------------------------------------------------------
__global__ void cnt_count(const void* __restrict__ ei, int e) {
    int i = blockIdx.x * blockDim.x + threadIdx.x;
    if (i < e) atomicAdd(&g_cnt[load_idx(ei, e, 1, i)], 1);
}

__global__ __launch_bounds__(256) void scan1(int n) {
    __shared__ int warp_sums[8];
    int tid = threadIdx.x;
    int base = blockIdx.x * 2048 + tid * 8;
    int v[8];
    int tot = 0;
#pragma unroll
    for (int i = 0; i < 8; i++) {
        int idx = base + i;
        v[i] = (idx < n) ? g_cnt[idx] : 0;
        tot += v[i];
    }
    int lane = tid & 31, wid = tid >> 5;
    int x = tot;
#pragma unroll
    for (int o = 1; o < 32; o <<= 1) {
        int y = __shfl_up_sync(0xFFFFFFFFu, x, o);
        if (lane >= o) x += y;
    }
    if (lane == 31) warp_sums[wid] = x;
    __syncthreads();
    if (wid == 0) {
        int w = (lane < 8) ? warp_sums[lane] : 0;
#pragma unroll
        for (int o = 1; o < 8; o <<= 1) {
            int y = __shfl_up_sync(0xFFFFFFFFu, w, o);
            if (lane >= o && lane < 8) w += y;
        }
        if (lane < 8) warp_sums[lane] = w;
    }
    __syncthreads();
    int excl = x - tot + ((wid > 0) ? warp_sums[wid - 1] : 0);
    int run = excl;
#pragma unroll
    for (int i = 0; i < 8; i++) {
        int idx = base + i;
        if (idx < n) g_off[idx] = run;
        run += v[i];
    }
    if (tid == 255) g_bsum[blockIdx.x] = excl + tot;
}

__global__ void scan2(int nb) {
    if (threadIdx.x == 0 && blockIdx.x == 0) {
        int run = 0;
        for (int i = 0; i < nb; i++) {
            int t = g_bsum[i];
            g_bsum[i] = run;
            run += t;
        }
    }
}

__global__ void scan3(int n) {
    int i = blockIdx.x * blockDim.x + threadIdx.x;
    if (i < n) {
        int o = g_off[i] + g_bsum[i >> 11];
        g_off[i]    = o;
        g_cursor[i] = o;
        g_dinv[i]   = rsqrtf((float)(g_cnt[i] + 1));   // +1 self-loop
    }
}

__global__ void scatter(const void* __restrict__ ei, int e) {
    int i = blockIdx.x * blockDim.x + threadIdx.x;
    if (i < e) {
        int s = load_idx(ei, e, 0, i);
        int d = load_idx(ei, e, 1, i);
        int p = atomicAdd(&g_cursor[d], 1);
        g_es[p] = s;
    }
}

__global__ void bn_prep(const float* __restrict__ b1, const float* __restrict__ gamma,
                        const float* __restrict__ beta, const float* __restrict__ mean,
                        const float* __restrict__ var) {
    int i = threadIdx.x;
    if (i < D) {
        float rs = rsqrtf(var[i] + BN_EPS);
        float s = rs * gamma[i];
        g_bn_s[i] = s;
        g_bn_t[i] = (b1[i] - mean[i]) * s + beta[i];
    }
}

// ---------------------------------------------------------------------------
// Packed-f32x2 SIMT GEMM: g_A = fp16(X @ W).
// layer==0: X = x_in (fp32) ; layer==1: X = g_Ch (fp16).
// BM=64, BN=128, BK=32; 256 threads.
// Accumulators are (row-pair, col) f32x2 packs:
//   A row-pairs come free via LDS.64 from transposed As;
//   B broadcast-pairs come from a duplicated smem image of W.
// ---------------------------------------------------------------------------
#define BM 64
#define BK 32

__device__ __forceinline__ void fma2(uint64_t& c, uint64_t a, uint64_t b) {
    asm("fma.rn.f32x2 %0, %1, %2, %0;" : "+l"(c) : "l"(a), "l"(b));
}

__global__ __launch_bounds__(256) void gemm128(const float* __restrict__ x_in,
                                               const float* __restrict__ W,
                                               int layer, int n) {
    __shared__ float As[BK][BM + 4];     // transposed x tile, padded
    __shared__ float Bsd[BK][2 * D];     // W tile with each value duplicated

    int tid = threadIdx.x;
    int tx = tid & 31;   // column group (4 cols each)
    int ty = tid >> 5;   // row group (8 rows each)
    int blockM = blockIdx.x * BM;

    uint64_t acc[4][4];  // [row-pair p: rows ty*8+2p,+2p+1][col j: tx*4+j]
#pragma unroll
    for (int p = 0; p < 4; p++)
#pragma unroll
        for (int j = 0; j < 4; j++) acc[p][j] = 0ULL;

    for (int k0 = 0; k0 < D; k0 += BK) {
        // Load X tile 64x32 (transposed into As[k][m])
#pragma unroll
        for (int r = 0; r < 2; r++) {
            int i   = tid + 256 * r;
            int row = i >> 3;
            int c4  = i & 7;
            float4 v = make_float4(0.f, 0.f, 0.f, 0.f);
            int gr = blockM + row;
            if (gr < n) {
                if (layer == 0) {
                    v = *(const float4*)&x_in[(size_t)gr * D + k0 + c4 * 4];
                } else {
                    uint2 u = *(const uint2*)&g_Ch[(size_t)gr * D + k0 + c4 * 4];
                    float2 a = __half22float2(*(__half2*)&u.x);
                    float2 b = __half22float2(*(__half2*)&u.y);
                    v.x = a.x; v.y = a.y; v.z = b.x; v.w = b.y;
                }
            }
            As[c4 * 4 + 0][row] = v.x;
            As[c4 * 4 + 1][row] = v.y;
            As[c4 * 4 + 2][row] = v.z;
            As[c4 * 4 + 3][row] = v.w;
        }
        // Load W tile 32x128, duplicated: Bsd[k][2c] = Bsd[k][2c+1] = W[k][c]
#pragma unroll
        for (int r = 0; r < 4; r++) {
            int i   = tid + 256 * r;
            int row = i >> 5;
            int c4  = i & 31;
            float4 v = *(const float4*)&W[(size_t)(k0 + row) * D + c4 * 4];
            float4 d0 = make_float4(v.x, v.x, v.y, v.y);
            float4 d1 = make_float4(v.z, v.z, v.w, v.w);
            *(float4*)&Bsd[row][c4 * 8]     = d0;
            *(float4*)&Bsd[row][c4 * 8 + 4] = d1;
        }
        __syncthreads();

#pragma unroll
        for (int k = 0; k < BK; k++) {
            const uint64_t* ap = (const uint64_t*)&As[k][ty * 8];   // 4 row-pairs
            uint64_t a0 = ap[0], a1 = ap[1], a2 = ap[2], a3 = ap[3];
            const uint64_t* bp = (const uint64_t*)&Bsd[k][tx * 8];  // 4 dup pairs
            uint64_t b0 = bp[0], b1 = bp[1], b2 = bp[2], b3 = bp[3];
            fma2(acc[0][0], a0, b0); fma2(acc[0][1], a0, b1);
            fma2(acc[0][2], a0, b2); fma2(acc[0][3], a0, b3);
            fma2(acc[1][0], a1, b0); fma2(acc[1][1], a1, b1);
            fma2(acc[1][2], a1, b2); fma2(acc[1][3], a1, b3);
            fma2(acc[2][0], a2, b0); fma2(acc[2][1], a2, b1);
            fma2(acc[2][2], a2, b2); fma2(acc[2][3], a2, b3);
            fma2(acc[3][0], a3, b0); fma2(acc[3][1], a3, b1);
            fma2(acc[3][2], a3, b2); fma2(acc[3][3], a3, b3);
        }
        __syncthreads();
    }

    // Epilogue: unpack pairs (lo = row 2p, hi = row 2p+1), store fp16.
#pragma unroll
    for (int p = 0; p < 4; p++) {
        int r0 = blockM + ty * 8 + 2 * p;
        int r1 = r0 + 1;
        float lo[4], hi[4];
#pragma unroll
        for (int j = 0; j < 4; j++) {
            lo[j] = __uint_as_float((uint32_t)acc[p][j]);
            hi[j] = __uint_as_float((uint32_t)(acc[p][j] >> 32));
        }
        if (r0 < n) {
            __half2 h0 = __floats2half2_rn(lo[0], lo[1]);
            __half2 h1 = __floats2half2_rn(lo[2], lo[3]);
            uint2 u; u.x = *(uint32_t*)&h0; u.y = *(uint32_t*)&h1;
            *(uint2*)&g_A[(size_t)r0 * D + tx * 4] = u;
        }
        if (r1 < n) {
            __half2 h0 = __floats2half2_rn(hi[0], hi[1]);
            __half2 h1 = __floats2half2_rn(hi[2], hi[3]);
            uint2 u; u.x = *(uint32_t*)&h0; u.y = *(uint32_t*)&h1;
            *(uint2*)&g_A[(size_t)r1 * D + tx * 4] = u;
        }
    }
}

// ---------------------------------------------------------------------------
// Gather helper: 16 lanes per row, uint4 = 8 halves (16B) per lane,
// weighted by scalar w (= dinv[src]).
// ---------------------------------------------------------------------------
__device__ __forceinline__ void gather8w(float* acc, int row, int hl, float w) {
    uint4 u = *(const uint4*)&g_A[(size_t)row * D + hl * 8];
    float2 a = __half22float2(*(__half2*)&u.x);
    float2 b = __half22float2(*(__half2*)&u.y);
    float2 c = __half22float2(*(__half2*)&u.z);
    float2 d = __half22float2(*(__half2*)&u.w);
    acc[0] = fmaf(w, a.x, acc[0]); acc[1] = fmaf(w, a.y, acc[1]);
    acc[2] = fmaf(w, b.x, acc[2]); acc[3] = fmaf(w, b.y, acc[3]);
    acc[4] = fmaf(w, c.x, acc[4]); acc[5] = fmaf(w, c.y, acc[5]);
    acc[6] = fmaf(w, d.x, acc[6]); acc[7] = fmaf(w, d.y, acc[7]);
}

// Warp-cooperative segmented weighted sum. Two edges concurrently (one per
// warp half), unrolled x2. Lanes 0-15 hold combined sums on return.
__device__ __forceinline__ void agg_node(float* acc, int node, int beg, int cnt,
                                         int half, int hl, float dinv_d) {
    if (half == 0) gather8w(acc, node, hl, dinv_d);   // self-loop

    int j = half;
    for (; j + 2 < cnt; j += 4) {
        int s0 = g_es[beg + j];
        int s1 = g_es[beg + j + 2];
        float w0 = g_dinv[s0];
        float w1 = g_dinv[s1];
        gather8w(acc, s0, hl, w0);
        gather8w(acc, s1, hl, w1);
    }
    for (; j < cnt; j += 2) {
        int s0 = g_es[beg + j];
        gather8w(acc, s0, hl, g_dinv[s0]);
    }

#pragma unroll
    for (int t = 0; t < 8; t++)
        acc[t] += __shfl_xor_sync(0xFFFFFFFFu, acc[t], 16);
}

// ---------------------------------------------------------------------------
// agg1: warp per node, fused BN+ReLU, fp16 output.
// ---------------------------------------------------------------------------
__global__ __launch_bounds__(256) void agg1(int n) {
    __shared__ float s_s[D], s_t[D];
    if (threadIdx.x < D) {
        s_s[threadIdx.x] = g_bn_s[threadIdx.x];
        s_t[threadIdx.x] = g_bn_t[threadIdx.x];
    }
    __syncthreads();

    int idx  = blockIdx.x * blockDim.x + threadIdx.x;
    int node = idx >> 5;
    int lane = idx & 31;
    if (node >= n) return;
    int half = lane >> 4;
    int hl   = lane & 15;

    float di = g_dinv[node];
    float acc[8] = {0.f, 0.f, 0.f, 0.f, 0.f, 0.f, 0.f, 0.f};
    agg_node(acc, node, g_off[node], g_cnt[node], half, hl, di);

    if (half == 0) {
        int col = hl * 8;
        __half2 h[4];
#pragma unroll
        for (int t = 0; t < 4; t++) {
            float r0 = fmaxf(acc[2*t]   * di * s_s[col + 2*t]   + s_t[col + 2*t],   0.f);
            float r1 = fmaxf(acc[2*t+1] * di * s_s[col + 2*t+1] + s_t[col + 2*t+1], 0.f);
            h[t] = __floats2half2_rn(r0, r1);
        }
        uint4 u;
        u.x = *(uint32_t*)&h[0]; u.y = *(uint32_t*)&h[1];
        u.z = *(uint32_t*)&h[2]; u.w = *(uint32_t*)&h[3];
        *(uint4*)&g_Ch[(size_t)node * D + col] = u;
    }
}

// ---------------------------------------------------------------------------
// agg2 + final fused: warp per node (grid-stride).
// ---------------------------------------------------------------------------
__global__ __launch_bounds__(256) void agg2_final(const float* __restrict__ b2,
                                                  const float* __restrict__ Wf,
                                                  const float* __restrict__ bf,
                                                  float* __restrict__ out,
                                                  int n) {
    __shared__ float Wfs[D][64];
    __shared__ float bfs[64];

    for (int i = threadIdx.x; i < D * 64; i += blockDim.x) {
        int r = i >> 6, c = i & 63;
        Wfs[r][c] = (c < DOUT) ? Wf[r * DOUT + c] : 0.0f;
    }
    if (threadIdx.x < 64)
        bfs[threadIdx.x] = (threadIdx.x < DOUT) ? bf[threadIdx.x] : 0.0f;
    __syncthreads();

    int lane = threadIdx.x & 31;
    int wid  = threadIdx.x >> 5;
    int wpb  = blockDim.x >> 5;
    int half = lane >> 4;
    int hl   = lane & 15;

    float4 bb0 = *(const float4*)&b2[hl * 8];
    float4 bb1 = *(const float4*)&b2[hl * 8 + 4];
    float bbv[8] = {bb0.x, bb0.y, bb0.z, bb0.w, bb1.x, bb1.y, bb1.z, bb1.w};

    for (int node = blockIdx.x * wpb + wid; node < n; node += gridDim.x * wpb) {
        float di = g_dinv[node];
        float acc[8] = {0.f, 0.f, 0.f, 0.f, 0.f, 0.f, 0.f, 0.f};
        agg_node(acc, node, g_off[node], g_cnt[node], half, hl, di);

        float jk[8];
        if (half == 0) {
            uint4 u = *(const uint4*)&g_Ch[(size_t)node * D + hl * 8];
            float2 a = __half22float2(*(__half2*)&u.x);
            float2 b = __half22float2(*(__half2*)&u.y);
            float2 c = __half22float2(*(__half2*)&u.z);
            float2 d = __half22float2(*(__half2*)&u.w);
            float h1v[8] = {a.x, a.y, b.x, b.y, c.x, c.y, d.x, d.y};
#pragma unroll
            for (int t = 0; t < 8; t++)
                jk[t] = fmaxf(h1v[t], acc[t] * di + bbv[t]);
        } else {
#pragma unroll
            for (int t = 0; t < 8; t++) jk[t] = 0.f;   // never sourced
        }

        float acc0 = 0.f, acc1 = 0.f;
#pragma unroll
        for (int k = 0; k < D; k++) {
            float v = __shfl_sync(0xFFFFFFFFu, jk[k & 7], k >> 3);
            acc0 += v * Wfs[k][lane];
            acc1 += v * Wfs[k][lane + 32];
        }
        acc0 += bfs[lane];
        acc1 += bfs[lane + 32];

        bool v0 = (lane < DOUT);
        bool v1 = (lane + 32 < DOUT);
        float m = fmaxf(v0 ? acc0 : -CUDART_INF_F, v1 ? acc1 : -CUDART_INF_F);
#pragma unroll
        for (int o = 16; o; o >>= 1) m = fmaxf(m, __shfl_xor_sync(0xFFFFFFFFu, m, o));
        float se = (v0 ? expf(acc0 - m) : 0.f) + (v1 ? expf(acc1 - m) : 0.f);
#pragma unroll
        for (int o = 16; o; o >>= 1) se += __shfl_xor_sync(0xFFFFFFFFu, se, o);
        float lse = m + logf(se);

        if (v0) out[(size_t)node * DOUT + lane] = acc0 - lse;
        if (v1) out[(size_t)node * DOUT + lane + 32] = acc1 - lse;
    }
}

// ---------------------------------------------------------------------------
// Launch: sort chain forked onto a side stream (kept from R9; harmless).
// ---------------------------------------------------------------------------
extern "C" void kernel_launch(void* const* d_in, const int* in_sizes, int n_in,
                              void* d_out, int out_size) {
    const float* x     = (const float*)d_in[0];
    const void*  ei    = d_in[1];
    const float* W1    = (const float*)d_in[2];
    const float* b1    = (const float*)d_in[3];
    const float* gamma = (const float*)d_in[4];
    const float* beta  = (const float*)d_in[5];
    const float* mean  = (const float*)d_in[6];
    const float* var   = (const float*)d_in[7];
    const float* W2    = (const float*)d_in[8];
    const float* b2    = (const float*)d_in[9];
    const float* Wf    = (const float*)d_in[10];
    const float* bf    = (const float*)d_in[11];
    float* out = (float*)d_out;

    int n = in_sizes[0] / D;
    int e = in_sizes[1] / 2;

    static cudaStream_t s_side = nullptr;
    static cudaEvent_t  ev_fork = nullptr, ev_join = nullptr;
    if (!s_side) {
        cudaStreamCreateWithFlags(&s_side, cudaStreamNonBlocking);
        cudaEventCreateWithFlags(&ev_fork, cudaEventDisableTiming);
        cudaEventCreateWithFlags(&ev_join, cudaEventDisableTiming);
    }

    int gemm_grid = (n + BM - 1) / BM;
    int agg_grid  = (n * 32 + 255) / 256;   // warp per node
    int nb = (n + 2047) / 2048;

    // Fork: side stream runs the sort/degree/BN chain.
    cudaEventRecord(ev_fork, 0);
    cudaStreamWaitEvent(s_side, ev_fork, 0);

    cnt_zero_detect<<<(n + 255) / 256, 256, 0, s_side>>>((const unsigned int*)ei, e, n);
    cnt_count<<<(e + 255) / 256, 256, 0, s_side>>>(ei, e);
    scan1<<<nb, 256, 0, s_side>>>(n);
    scan2<<<1, 32, 0, s_side>>>(nb);
    scan3<<<(n + 255) / 256, 256, 0, s_side>>>(n);
    scatter<<<(e + 255) / 256, 256, 0, s_side>>>(ei, e);
    bn_prep<<<1, 128, 0, s_side>>>(b1, gamma, beta, mean, var);
    cudaEventRecord(ev_join, s_side);

    // Main stream: GEMM1 (independent of the sort chain).
    gemm128<<<gemm_grid, 256>>>(x, W1, 0, n);

    // Join, then the dependent tail.
    cudaStreamWaitEvent(0, ev_join, 0);
    agg1<<<agg_grid, 256>>>(n);
    gemm128<<<gemm_grid, 256>>>(nullptr, W2, 1, n);
    agg2_final<<<1036, 256>>>(b2, Wf, bf, out, n);
}

// round 13
// speedup vs baseline: 1.4139x; 1.4139x over previous
#include <cuda_runtime.h>
#include <cuda_fp16.h>
#include <math_constants.h>
#include <cstdint>

// Problem constants
#define MAXN 100000
#define MAXE 1600000
#define D 128
#define DOUT 47
#define BN_EPS 1e-5f

// Scratch (device globals; allocation-free per harness rules)
__device__ __half g_A[(size_t)MAXN * D];   // GEMM output (unscaled), fp16
__device__ __half g_Ch[(size_t)MAXN * D];  // h1 (post BN+ReLU), fp16
__device__ float  g_dinv[MAXN];            // 1/sqrt(deg)
__device__ float  g_bn_s[D];               // fused BN scale
__device__ float  g_bn_t[D];               // fused BN bias
__device__ int    g_cnt[MAXN];             // dst histogram (edges only)
__device__ int    g_off[MAXN];             // exclusive prefix of g_cnt
__device__ int    g_cursor[MAXN];          // scatter cursors
__device__ int    g_es[MAXE];              // src ids, sorted by dst
__device__ int    g_bsum[64];              // scan block sums
__device__ int    g_is64;                  // edge_index dtype flag

// ---------------------------------------------------------------------------
// cnt_zero + edge-index dtype detection fused.
// ---------------------------------------------------------------------------
__global__ void cnt_zero_detect(const unsigned int* __restrict__ ei32, int e, int n) {
    int i = blockIdx.x * blockDim.x + threadIdx.x;
    if (i < n) g_cnt[i] = 0;
    if (blockIdx.x == 0 && threadIdx.x == 0) {
        int is64 = 1;
        int lim = (e < 64) ? e : 64;
        for (int k = 0; k < lim; k++) {
            if (ei32[2 * k + 1] != 0u) { is64 = 0; break; }
        }
        g_is64 = is64;
    }
}

__device__ __forceinline__ int load_idx(const void* __restrict__ ei, int e,
                                        int which, int i) {
    if (g_is64) {
        const long long* p = (const long long*)ei;
        return (int)p[(size_t)which * e + i];
    } else {
        const int* p = (const int*)ei;
        return p[(size_t)which * e + i];
    }
}

// ---------------------------------------------------------------------------
// Counting sort by dst: histogram -> scan -> scatter ; degrees ; BN prep
// ---------------------------------------------------------------------------
__global__ void cnt_count(const void* __restrict__ ei, int e) {
    int i = blockIdx.x * blockDim.x + threadIdx.x;
    if (i < e) atomicAdd(&g_cnt[load_idx(ei, e, 1, i)], 1);
}

__global__ __launch_bounds__(256) void scan1(int n) {
    __shared__ int warp_sums[8];
    int tid = threadIdx.x;
    int base = blockIdx.x * 2048 + tid * 8;
    int v[8];
    int tot = 0;
#pragma unroll
    for (int i = 0; i < 8; i++) {
        int idx = base + i;
        v[i] = (idx < n) ? g_cnt[idx] : 0;
        tot += v[i];
    }
    int lane = tid & 31, wid = tid >> 5;
    int x = tot;
#pragma unroll
    for (int o = 1; o < 32; o <<= 1) {
        int y = __shfl_up_sync(0xFFFFFFFFu, x, o);
        if (lane >= o) x += y;
    }
    if (lane == 31) warp_sums[wid] = x;
    __syncthreads();
    if (wid == 0) {
        int w = (lane < 8) ? warp_sums[lane] : 0;
#pragma unroll
        for (int o = 1; o < 8; o <<= 1) {
            int y = __shfl_up_sync(0xFFFFFFFFu, w, o);
            if (lane >= o && lane < 8) w += y;
        }
        if (lane < 8) warp_sums[lane] = w;
    }
    __syncthreads();
    int excl = x - tot + ((wid > 0) ? warp_sums[wid - 1] : 0);
    int run = excl;
#pragma unroll
    for (int i = 0; i < 8; i++) {
        int idx = base + i;
        if (idx < n) g_off[idx] = run;
        run += v[i];
    }
    if (tid == 255) g_bsum[blockIdx.x] = excl + tot;
}

__global__ void scan2(int nb) {
    if (threadIdx.x == 0 && blockIdx.x == 0) {
        int run = 0;
        for (int i = 0; i < nb; i++) {
            int t = g_bsum[i];
            g_bsum[i] = run;
            run += t;
        }
    }
}

__global__ void scan3(int n) {
    int i = blockIdx.x * blockDim.x + threadIdx.x;
    if (i < n) {
        int o = g_off[i] + g_bsum[i >> 11];
        g_off[i]    = o;
        g_cursor[i] = o;
        g_dinv[i]   = rsqrtf((float)(g_cnt[i] + 1));   // +1 self-loop
    }
}

__global__ void scatter(const void* __restrict__ ei, int e) {
    int i = blockIdx.x * blockDim.x + threadIdx.x;
    if (i < e) {
        int s = load_idx(ei, e, 0, i);
        int d = load_idx(ei, e, 1, i);
        int p = atomicAdd(&g_cursor[d], 1);
        g_es[p] = s;
    }
}

__global__ void bn_prep(const float* __restrict__ b1, const float* __restrict__ gamma,
                        const float* __restrict__ beta, const float* __restrict__ mean,
                        const float* __restrict__ var) {
    int i = threadIdx.x;
    if (i < D) {
        float rs = rsqrtf(var[i] + BN_EPS);
        float s = rs * gamma[i];
        g_bn_s[i] = s;
        g_bn_t[i] = (b1[i] - mean[i]) * s + beta[i];
    }
}

// ---------------------------------------------------------------------------
// HFMA2 GEMM: g_A = fp16(X @ W), fp16 math, per-BK-chunk fp32 accumulation.
// layer==0: X = x_in (fp32, converted on load) ; layer==1: X = g_Ch (fp16).
// BM=64, BN=128, BK=32; 256 threads; 8 rows x 4 cols per thread.
// Inner loop: 16 HFMA2 per k (2 MACs each) vs 32 FFMA before.
// ---------------------------------------------------------------------------
#define BM 64
#define BK 32
#define ASP (BM + 8)    // As row stride in halves
#define BSP (D + 8)     // Bs row stride in halves

__global__ __launch_bounds__(256) void gemm128(const float* __restrict__ x_in,
                                               const float* __restrict__ W,
                                               int layer, int n) {
    __shared__ __half As[BK][ASP];   // transposed x tile: As[k][m]
    __shared__ __half Bs[BK][BSP];   // W tile: Bs[k][c]

    int tid = threadIdx.x;
    int tx = tid & 31;   // column group (4 cols each)
    int ty = tid >> 5;   // row group (8 rows each)
    int blockM = blockIdx.x * BM;

    float acc32[8][4];
#pragma unroll
    for (int i = 0; i < 8; i++)
#pragma unroll
        for (int j = 0; j < 4; j++) acc32[i][j] = 0.0f;

    for (int k0 = 0; k0 < D; k0 += BK) {
        // Load X tile 64x32 -> fp16, transposed into As[k][m]
#pragma unroll
        for (int r = 0; r < 2; r++) {
            int i   = tid + 256 * r;
            int row = i >> 3;
            int c4  = i & 7;
            __half h[4];
            int gr = blockM + row;
            if (gr < n) {
                if (layer == 0) {
                    float4 v = *(const float4*)&x_in[(size_t)gr * D + k0 + c4 * 4];
                    h[0] = __float2half_rn(v.x); h[1] = __float2half_rn(v.y);
                    h[2] = __float2half_rn(v.z); h[3] = __float2half_rn(v.w);
                } else {
                    uint2 u = *(const uint2*)&g_Ch[(size_t)gr * D + k0 + c4 * 4];
                    __half2 p0 = *(__half2*)&u.x;
                    __half2 p1 = *(__half2*)&u.y;
                    h[0] = __low2half(p0); h[1] = __high2half(p0);
                    h[2] = __low2half(p1); h[3] = __high2half(p1);
                }
            } else {
                h[0] = h[1] = h[2] = h[3] = __float2half_rn(0.f);
            }
#pragma unroll
            for (int j = 0; j < 4; j++) As[c4 * 4 + j][row] = h[j];
        }
        // Load W tile 32x128 -> fp16
#pragma unroll
        for (int r = 0; r < 4; r++) {
            int i   = tid + 256 * r;
            int row = i >> 5;
            int c4  = i & 31;
            float4 v = *(const float4*)&W[(size_t)(k0 + row) * D + c4 * 4];
            __half2 p0 = __floats2half2_rn(v.x, v.y);
            __half2 p1 = __floats2half2_rn(v.z, v.w);
            uint2 u; u.x = *(uint32_t*)&p0; u.y = *(uint32_t*)&p1;
            *(uint2*)&Bs[row][c4 * 4] = u;
        }
        __syncthreads();

        // fp16 chunk accumulators (reset per BK tile)
        __half2 acc16[8][2];
#pragma unroll
        for (int i = 0; i < 8; i++) {
            acc16[i][0] = __floats2half2_rn(0.f, 0.f);
            acc16[i][1] = __floats2half2_rn(0.f, 0.f);
        }

#pragma unroll
        for (int k = 0; k < BK; k++) {
            uint4 au = *(const uint4*)&As[k][ty * 8];   // 8 rows (4 half2)
            __half2 ap[4];
            ap[0] = *(__half2*)&au.x; ap[1] = *(__half2*)&au.y;
            ap[2] = *(__half2*)&au.z; ap[3] = *(__half2*)&au.w;
            uint2 bu = *(const uint2*)&Bs[k][tx * 4];   // 4 cols (2 half2)
            __half2 b0 = *(__half2*)&bu.x;
            __half2 b1 = *(__half2*)&bu.y;
#pragma unroll
            for (int rp = 0; rp < 4; rp++) {
                __half2 al = __low2half2(ap[rp]);    // row 2rp dup -> .H0_H0
                __half2 ah = __high2half2(ap[rp]);   // row 2rp+1 dup -> .H1_H1
                acc16[2*rp+0][0] = __hfma2(al, b0, acc16[2*rp+0][0]);
                acc16[2*rp+0][1] = __hfma2(al, b1, acc16[2*rp+0][1]);
                acc16[2*rp+1][0] = __hfma2(ah, b0, acc16[2*rp+1][0]);
                acc16[2*rp+1][1] = __hfma2(ah, b1, acc16[2*rp+1][1]);
            }
        }

        // Spill chunk into fp32 accumulators
#pragma unroll
        for (int i = 0; i < 8; i++) {
            float2 f0 = __half22float2(acc16[i][0]);
            float2 f1 = __half22float2(acc16[i][1]);
            acc32[i][0] += f0.x; acc32[i][1] += f0.y;
            acc32[i][2] += f1.x; acc32[i][3] += f1.y;
        }
        __syncthreads();
    }

#pragma unroll
    for (int i = 0; i < 8; i++) {
        int row = blockM + ty * 8 + i;
        if (row < n) {
            __half2 h0 = __floats2half2_rn(acc32[i][0], acc32[i][1]);
            __half2 h1 = __floats2half2_rn(acc32[i][2], acc32[i][3]);
            uint2 u;
            u.x = *(uint32_t*)&h0;
            u.y = *(uint32_t*)&h1;
            *(uint2*)&g_A[(size_t)row * D + tx * 4] = u;
        }
    }
}

// ---------------------------------------------------------------------------
// Gather helper: 16 lanes per row, uint4 = 8 halves (16B) per lane,
// weighted by scalar w (= dinv[src]).
// ---------------------------------------------------------------------------
__device__ __forceinline__ void gather8w(float* acc, int row, int hl, float w) {
    uint4 u = *(const uint4*)&g_A[(size_t)row * D + hl * 8];
    float2 a = __half22float2(*(__half2*)&u.x);
    float2 b = __half22float2(*(__half2*)&u.y);
    float2 c = __half22float2(*(__half2*)&u.z);
    float2 d = __half22float2(*(__half2*)&u.w);
    acc[0] = fmaf(w, a.x, acc[0]); acc[1] = fmaf(w, a.y, acc[1]);
    acc[2] = fmaf(w, b.x, acc[2]); acc[3] = fmaf(w, b.y, acc[3]);
    acc[4] = fmaf(w, c.x, acc[4]); acc[5] = fmaf(w, c.y, acc[5]);
    acc[6] = fmaf(w, d.x, acc[6]); acc[7] = fmaf(w, d.y, acc[7]);
}

// Warp-cooperative segmented weighted sum. Two edges concurrently (one per
// warp half), unrolled x2. Lanes 0-15 hold combined sums on return.
__device__ __forceinline__ void agg_node(float* acc, int node, int beg, int cnt,
                                         int half, int hl, float dinv_d) {
    if (half == 0) gather8w(acc, node, hl, dinv_d);   // self-loop

    int j = half;
    for (; j + 2 < cnt; j += 4) {
        int s0 = g_es[beg + j];
        int s1 = g_es[beg + j + 2];
        float w0 = g_dinv[s0];
        float w1 = g_dinv[s1];
        gather8w(acc, s0, hl, w0);
        gather8w(acc, s1, hl, w1);
    }
    for (; j < cnt; j += 2) {
        int s0 = g_es[beg + j];
        gather8w(acc, s0, hl, g_dinv[s0]);
    }

#pragma unroll
    for (int t = 0; t < 8; t++)
        acc[t] += __shfl_xor_sync(0xFFFFFFFFu, acc[t], 16);
}

// ---------------------------------------------------------------------------
// agg1: warp per node, fused BN+ReLU, fp16 output.
// ---------------------------------------------------------------------------
__global__ __launch_bounds__(256) void agg1(int n) {
    __shared__ float s_s[D], s_t[D];
    if (threadIdx.x < D) {
        s_s[threadIdx.x] = g_bn_s[threadIdx.x];
        s_t[threadIdx.x] = g_bn_t[threadIdx.x];
    }
    __syncthreads();

    int idx  = blockIdx.x * blockDim.x + threadIdx.x;
    int node = idx >> 5;
    int lane = idx & 31;
    if (node >= n) return;
    int half = lane >> 4;
    int hl   = lane & 15;

    float di = g_dinv[node];
    float acc[8] = {0.f, 0.f, 0.f, 0.f, 0.f, 0.f, 0.f, 0.f};
    agg_node(acc, node, g_off[node], g_cnt[node], half, hl, di);

    if (half == 0) {
        int col = hl * 8;
        __half2 h[4];
#pragma unroll
        for (int t = 0; t < 4; t++) {
            float r0 = fmaxf(acc[2*t]   * di * s_s[col + 2*t]   + s_t[col + 2*t],   0.f);
            float r1 = fmaxf(acc[2*t+1] * di * s_s[col + 2*t+1] + s_t[col + 2*t+1], 0.f);
            h[t] = __floats2half2_rn(r0, r1);
        }
        uint4 u;
        u.x = *(uint32_t*)&h[0]; u.y = *(uint32_t*)&h[1];
        u.z = *(uint32_t*)&h[2]; u.w = *(uint32_t*)&h[3];
        *(uint4*)&g_Ch[(size_t)node * D + col] = u;
    }
}

// ---------------------------------------------------------------------------
// agg2 + final fused: warp per node (grid-stride).
// ---------------------------------------------------------------------------
__global__ __launch_bounds__(256) void agg2_final(const float* __restrict__ b2,
                                                  const float* __restrict__ Wf,
                                                  const float* __restrict__ bf,
                                                  float* __restrict__ out,
                                                  int n) {
    __shared__ float Wfs[D][64];
    __shared__ float bfs[64];

    for (int i = threadIdx.x; i < D * 64; i += blockDim.x) {
        int r = i >> 6, c = i & 63;
        Wfs[r][c] = (c < DOUT) ? Wf[r * DOUT + c] : 0.0f;
    }
    if (threadIdx.x < 64)
        bfs[threadIdx.x] = (threadIdx.x < DOUT) ? bf[threadIdx.x] : 0.0f;
    __syncthreads();

    int lane = threadIdx.x & 31;
    int wid  = threadIdx.x >> 5;
    int wpb  = blockDim.x >> 5;
    int half = lane >> 4;
    int hl   = lane & 15;

    float4 bb0 = *(const float4*)&b2[hl * 8];
    float4 bb1 = *(const float4*)&b2[hl * 8 + 4];
    float bbv[8] = {bb0.x, bb0.y, bb0.z, bb0.w, bb1.x, bb1.y, bb1.z, bb1.w};

    for (int node = blockIdx.x * wpb + wid; node < n; node += gridDim.x * wpb) {
        float di = g_dinv[node];
        float acc[8] = {0.f, 0.f, 0.f, 0.f, 0.f, 0.f, 0.f, 0.f};
        agg_node(acc, node, g_off[node], g_cnt[node], half, hl, di);

        float jk[8];
        if (half == 0) {
            uint4 u = *(const uint4*)&g_Ch[(size_t)node * D + hl * 8];
            float2 a = __half22float2(*(__half2*)&u.x);
            float2 b = __half22float2(*(__half2*)&u.y);
            float2 c = __half22float2(*(__half2*)&u.z);
            float2 d = __half22float2(*(__half2*)&u.w);
            float h1v[8] = {a.x, a.y, b.x, b.y, c.x, c.y, d.x, d.y};
#pragma unroll
            for (int t = 0; t < 8; t++)
                jk[t] = fmaxf(h1v[t], acc[t] * di + bbv[t]);
        } else {
#pragma unroll
            for (int t = 0; t < 8; t++) jk[t] = 0.f;   // never sourced
        }

        float acc0 = 0.f, acc1 = 0.f;
#pragma unroll
        for (int k = 0; k < D; k++) {
            float v = __shfl_sync(0xFFFFFFFFu, jk[k & 7], k >> 3);
            acc0 += v * Wfs[k][lane];
            acc1 += v * Wfs[k][lane + 32];
        }
        acc0 += bfs[lane];
        acc1 += bfs[lane + 32];

        bool v0 = (lane < DOUT);
        bool v1 = (lane + 32 < DOUT);
        float m = fmaxf(v0 ? acc0 : -CUDART_INF_F, v1 ? acc1 : -CUDART_INF_F);
#pragma unroll
        for (int o = 16; o; o >>= 1) m = fmaxf(m, __shfl_xor_sync(0xFFFFFFFFu, m, o));
        float se = (v0 ? expf(acc0 - m) : 0.f) + (v1 ? expf(acc1 - m) : 0.f);
#pragma unroll
        for (int o = 16; o; o >>= 1) se += __shfl_xor_sync(0xFFFFFFFFu, se, o);
        float lse = m + logf(se);

        if (v0) out[(size_t)node * DOUT + lane] = acc0 - lse;
        if (v1) out[(size_t)node * DOUT + lane + 32] = acc1 - lse;
    }
}

// ---------------------------------------------------------------------------
// Launch: sort chain forked onto a side stream (kept from R9; harmless).
// ---------------------------------------------------------------------------
extern "C" void kernel_launch(void* const* d_in, const int* in_sizes, int n_in,
                              void* d_out, int out_size) {
    const float* x     = (const float*)d_in[0];
    const void*  ei    = d_in[1];
    const float* W1    = (const float*)d_in[2];
    const float* b1    = (const float*)d_in[3];
    const float* gamma = (const float*)d_in[4];
    const float* beta  = (const float*)d_in[5];
    const float* mean  = (const float*)d_in[6];
    const float* var   = (const float*)d_in[7];
    const float* W2    = (const float*)d_in[8];
    const float* b2    = (const float*)d_in[9];
    const float* Wf    = (const float*)d_in[10];
    const float* bf    = (const float*)d_in[11];
    float* out = (float*)d_out;

    int n = in_sizes[0] / D;
    int e = in_sizes[1] / 2;

    static cudaStream_t s_side = nullptr;
    static cudaEvent_t  ev_fork = nullptr, ev_join = nullptr;
    if (!s_side) {
        cudaStreamCreateWithFlags(&s_side, cudaStreamNonBlocking);
        cudaEventCreateWithFlags(&ev_fork, cudaEventDisableTiming);
        cudaEventCreateWithFlags(&ev_join, cudaEventDisableTiming);
    }

    int gemm_grid = (n + BM - 1) / BM;
    int agg_grid  = (n * 32 + 255) / 256;   // warp per node
    int nb = (n + 2047) / 2048;

    // Fork: side stream runs the sort/degree/BN chain.
    cudaEventRecord(ev_fork, 0);
    cudaStreamWaitEvent(s_side, ev_fork, 0);

    cnt_zero_detect<<<(n + 255) / 256, 256, 0, s_side>>>((const unsigned int*)ei, e, n);
    cnt_count<<<(e + 255) / 256, 256, 0, s_side>>>(ei, e);
    scan1<<<nb, 256, 0, s_side>>>(n);
    scan2<<<1, 32, 0, s_side>>>(nb);
    scan3<<<(n + 255) / 256, 256, 0, s_side>>>(n);
    scatter<<<(e + 255) / 256, 256, 0, s_side>>>(ei, e);
    bn_prep<<<1, 128, 0, s_side>>>(b1, gamma, beta, mean, var);
    cudaEventRecord(ev_join, s_side);

    // Main stream: GEMM1 (independent of the sort chain).
    gemm128<<<gemm_grid, 256>>>(x, W1, 0, n);

    // Join, then the dependent tail.
    cudaStreamWaitEvent(0, ev_join, 0);
    agg1<<<agg_grid, 256>>>(n);
    gemm128<<<gemm_grid, 256>>>(nullptr, W2, 1, n);
    agg2_final<<<1036, 256>>>(b2, Wf, bf, out, n);
}